// round 1
// baseline (speedup 1.0000x reference)
#include <cuda_runtime.h>
#include <math.h>

#define B_   8192
#define DIN  1024
#define HID  2048
#define LAT  256
#define KC   4096

// ---------------- scratch (device globals; no allocation allowed) ----------
__device__ float g_h1[(size_t)B_ * HID];   // 64 MB
__device__ float g_h2[(size_t)B_ * HID];   // 64 MB
__device__ float g_ze[(size_t)B_ * LAT];   // 8 MB
__device__ float g_zq[(size_t)B_ * LAT];   // 8 MB
__device__ float g_zsq[B_];
__device__ float g_esq[KC];
__device__ float g_rowloss[B_];
__device__ int   g_idx[B_];

__device__ __forceinline__ float gelu_exact(float x) {
    // torch nn.GELU default: exact erf formulation
    return 0.5f * x * (1.0f + erff(x * 0.7071067811865476f));
}

// ---------------- SGEMM: C = act(A[M,K] @ B[K,N] + bias) --------------------
// 128x128 tile, BK=8, 256 threads, 8x8 per thread. All dims multiples of 128/8.
template<bool GELU>
__global__ void __launch_bounds__(256, 2) sgemm_bias_act(
    const float* __restrict__ A, const float* __restrict__ Bm,
    const float* __restrict__ bias, float* __restrict__ C,
    int M, int N, int K)
{
    __shared__ float As[8][128];
    __shared__ float Bs[8][128];

    const int tid = threadIdx.x;
    const int bm = blockIdx.y * 128;
    const int bn = blockIdx.x * 128;

    const int arow = tid >> 1;            // 0..127
    const int acol = (tid & 1) * 4;       // 0 or 4
    const int brow = tid >> 5;            // 0..7
    const int bcol = (tid & 31) * 4;      // 0..124

    const int ty = tid >> 4;              // 0..15
    const int tx = tid & 15;              // 0..15

    float acc[8][8];
#pragma unroll
    for (int i = 0; i < 8; i++)
#pragma unroll
        for (int j = 0; j < 8; j++) acc[i][j] = 0.0f;

    const float* Aptr = A + (size_t)(bm + arow) * K + acol;
    const float* Bptr = Bm + (size_t)brow * N + bn + bcol;

    for (int k0 = 0; k0 < K; k0 += 8) {
        float4 a4 = *(const float4*)(Aptr + k0);
        As[acol + 0][arow] = a4.x;
        As[acol + 1][arow] = a4.y;
        As[acol + 2][arow] = a4.z;
        As[acol + 3][arow] = a4.w;
        float4 b4 = *(const float4*)(Bptr + (size_t)k0 * N);
        *(float4*)&Bs[brow][bcol] = b4;
        __syncthreads();

#pragma unroll
        for (int kk = 0; kk < 8; kk++) {
            float ra[8], rb[8];
            *(float4*)(ra)     = *(const float4*)&As[kk][ty * 8];
            *(float4*)(ra + 4) = *(const float4*)&As[kk][ty * 8 + 4];
            *(float4*)(rb)     = *(const float4*)&Bs[kk][tx * 8];
            *(float4*)(rb + 4) = *(const float4*)&Bs[kk][tx * 8 + 4];
#pragma unroll
            for (int i = 0; i < 8; i++)
#pragma unroll
                for (int j = 0; j < 8; j++)
                    acc[i][j] = fmaf(ra[i], rb[j], acc[i][j]);
        }
        __syncthreads();
    }

#pragma unroll
    for (int i = 0; i < 8; i++) {
        int row = bm + ty * 8 + i;
#pragma unroll
        for (int j = 0; j < 8; j += 4) {
            int col = bn + tx * 8 + j;
            float4 v;
            v.x = acc[i][j + 0] + bias[col + 0];
            v.y = acc[i][j + 1] + bias[col + 1];
            v.z = acc[i][j + 2] + bias[col + 2];
            v.w = acc[i][j + 3] + bias[col + 3];
            if (GELU) {
                v.x = gelu_exact(v.x); v.y = gelu_exact(v.y);
                v.z = gelu_exact(v.z); v.w = gelu_exact(v.w);
            }
            *(float4*)(C + (size_t)row * N + col) = v;
        }
    }
}

// ---------------- per-row sum of squares (one warp per row) ----------------
__global__ void rowsumsq_kernel(const float* __restrict__ src,
                                float* __restrict__ out, int rows)
{
    int warp = (blockIdx.x * blockDim.x + threadIdx.x) >> 5;
    int lane = threadIdx.x & 31;
    if (warp >= rows) return;
    const float* p = src + (size_t)warp * LAT;
    float s = 0.0f;
#pragma unroll
    for (int i = 0; i < LAT; i += 32) {
        float v = p[i + lane];
        s = fmaf(v, v, s);
    }
#pragma unroll
    for (int o = 16; o; o >>= 1) s += __shfl_down_sync(0xffffffffu, s, o);
    if (lane == 0) out[warp] = s;
}

// ---------------- distance + argmin: 64 rows x 4096 codes per block --------
// dist = (zsq + esq) - 2*dot, rounded exactly like the reference's
// (z_sq + e_sq) - 2*(z@e^T) elementwise expression. First-index tie-break.
__global__ void __launch_bounds__(256) dist_argmin_kernel(
    const float* __restrict__ embed)
{
    extern __shared__ float sm[];
    float* Zs = sm;                 // [256][64] k-major
    float* Es = sm + 256 * 64;      // [256][64] k-major

    const int tid = threadIdx.x;
    const int row0 = blockIdx.x * 64;

    // load Z tile transposed
    for (int t = tid; t < 64 * 64; t += 256) {
        int r  = t & 63;
        int kq = t >> 6;            // float4 index along k
        float4 v = *(const float4*)(&g_ze[(size_t)(row0 + r) * LAT + kq * 4]);
        Zs[(kq * 4 + 0) * 64 + r] = v.x;
        Zs[(kq * 4 + 1) * 64 + r] = v.y;
        Zs[(kq * 4 + 2) * 64 + r] = v.z;
        Zs[(kq * 4 + 3) * 64 + r] = v.w;
    }

    const int ty = tid >> 4, tx = tid & 15;
    float bestv[4];
    int   besti[4];
#pragma unroll
    for (int i = 0; i < 4; i++) { bestv[i] = INFINITY; besti[i] = 0; }

    float zs[4];
#pragma unroll
    for (int i = 0; i < 4; i++) zs[i] = g_zsq[row0 + ty * 4 + i];

    for (int c0 = 0; c0 < KC; c0 += 64) {
        __syncthreads();
        for (int t = tid; t < 64 * 64; t += 256) {
            int r  = t & 63;
            int kq = t >> 6;
            float4 v = *(const float4*)(&embed[(size_t)(c0 + r) * LAT + kq * 4]);
            Es[(kq * 4 + 0) * 64 + r] = v.x;
            Es[(kq * 4 + 1) * 64 + r] = v.y;
            Es[(kq * 4 + 2) * 64 + r] = v.z;
            Es[(kq * 4 + 3) * 64 + r] = v.w;
        }
        __syncthreads();

        float acc[4][4];
#pragma unroll
        for (int i = 0; i < 4; i++)
#pragma unroll
            for (int j = 0; j < 4; j++) acc[i][j] = 0.0f;

        for (int k = 0; k < 256; k++) {
            float rz[4], re[4];
            *(float4*)rz = *(const float4*)&Zs[k * 64 + ty * 4];
            *(float4*)re = *(const float4*)&Es[k * 64 + tx * 4];
#pragma unroll
            for (int i = 0; i < 4; i++)
#pragma unroll
                for (int j = 0; j < 4; j++)
                    acc[i][j] = fmaf(rz[i], re[j], acc[i][j]);
        }

#pragma unroll
        for (int i = 0; i < 4; i++) {
#pragma unroll
            for (int j = 0; j < 4; j++) {
                int c = c0 + tx * 4 + j;
                float t1 = zs[i] + g_esq[c];          // fl(z_sq + e_sq)
                float v  = fmaf(-2.0f, acc[i][j], t1); // fl(t1 - 2*dot)
                if (v < bestv[i] || (v == bestv[i] && c < besti[i])) {
                    bestv[i] = v; besti[i] = c;
                }
            }
        }
    }

    // cross-thread reduction over the 16 tx owners of each row
    __syncthreads();
    float* sval = Es;                      // reuse smem
    int*   sidx = (int*)(Es + 64 * 16);
#pragma unroll
    for (int i = 0; i < 4; i++) {
        sval[(ty * 4 + i) * 16 + tx] = bestv[i];
        sidx[(ty * 4 + i) * 16 + tx] = besti[i];
    }
    __syncthreads();
    if (tid < 64) {
        float bv = INFINITY; int bi = 0x7fffffff;
        for (int t = 0; t < 16; t++) {
            float v = sval[tid * 16 + t];
            int   c = sidx[tid * 16 + t];
            if (v < bv || (v == bv && c < bi)) { bv = v; bi = c; }
        }
        g_idx[row0 + tid] = bi;
    }
}

// ---------------- gather z_q, per-row loss, indices out --------------------
__global__ void gather_loss_kernel(const float* __restrict__ embed,
                                   float* __restrict__ out_f, int write_extra)
{
    int warp = (blockIdx.x * blockDim.x + threadIdx.x) >> 5;
    int lane = threadIdx.x & 31;
    if (warp >= B_) return;
    int idx = g_idx[warp];
    const float* ze = g_ze + (size_t)warp * LAT;
    const float* eq = embed + (size_t)idx * LAT;
    float s = 0.0f;
#pragma unroll
    for (int i = 0; i < LAT; i += 32) {
        float q = eq[i + lane];
        float z = ze[i + lane];
        g_zq[(size_t)warp * LAT + i + lane] = q;
        float d = z - q;
        s = fmaf(d, d, s);
    }
#pragma unroll
    for (int o = 16; o; o >>= 1) s += __shfl_down_sync(0xffffffffu, s, o);
    if (lane == 0) {
        g_rowloss[warp] = s;
        if (write_extra)
            out_f[(size_t)B_ * DIN + 1 + warp] = (float)idx;
    }
}

// ---------------- final loss reduction (single block, fixed order) ---------
__global__ void loss_final_kernel(float* __restrict__ out_f, int write_extra)
{
    __shared__ float sh[256];
    float s = 0.0f;
    for (int i = threadIdx.x; i < B_; i += 256) s += g_rowloss[i];
    sh[threadIdx.x] = s;
    __syncthreads();
    for (int o = 128; o; o >>= 1) {
        if (threadIdx.x < o) sh[threadIdx.x] += sh[threadIdx.x + o];
        __syncthreads();
    }
    if (threadIdx.x == 0 && write_extra) {
        // vq_loss = codebook + 0.25*commitment = 1.25 * mean((z_e - z_q)^2)
        out_f[(size_t)B_ * DIN] = 1.25f * sh[0] / (float)((size_t)B_ * LAT);
    }
}

// ---------------- launch ----------------------------------------------------
extern "C" void kernel_launch(void* const* d_in, const int* in_sizes, int n_in,
                              void* d_out, int out_size)
{
    const float* x     = (const float*)d_in[0];
    const float* W1    = (const float*)d_in[1];
    const float* b1    = (const float*)d_in[2];
    const float* W2    = (const float*)d_in[3];
    const float* b2    = (const float*)d_in[4];
    const float* W3    = (const float*)d_in[5];
    const float* b3    = (const float*)d_in[6];
    const float* embed = (const float*)d_in[7];
    const float* D1    = (const float*)d_in[8];
    const float* d1    = (const float*)d_in[9];
    const float* D2    = (const float*)d_in[10];
    const float* d2    = (const float*)d_in[11];
    const float* D3    = (const float*)d_in[12];
    const float* d3    = (const float*)d_in[13];
    float* out = (float*)d_out;

    float *h1, *h2, *ze, *zq, *zsq, *esq;
    cudaGetSymbolAddress((void**)&h1,  g_h1);
    cudaGetSymbolAddress((void**)&h2,  g_h2);
    cudaGetSymbolAddress((void**)&ze,  g_ze);
    cudaGetSymbolAddress((void**)&zq,  g_zq);
    cudaGetSymbolAddress((void**)&zsq, g_zsq);
    cudaGetSymbolAddress((void**)&esq, g_esq);

    const int write_extra =
        ((size_t)out_size >= (size_t)B_ * DIN + 1 + B_) ? 1 : 0;

    // encoder
    {
        dim3 g(HID / 128, B_ / 128);
        sgemm_bias_act<true><<<g, 256>>>(x, W1, b1, h1, B_, HID, DIN);
    }
    {
        dim3 g(HID / 128, B_ / 128);
        sgemm_bias_act<true><<<g, 256>>>(h1, W2, b2, h2, B_, HID, HID);
    }
    {
        dim3 g(LAT / 128, B_ / 128);
        sgemm_bias_act<false><<<g, 256>>>(h2, W3, b3, ze, B_, LAT, HID);
    }

    // norms
    rowsumsq_kernel<<<(B_ * 32) / 256, 256>>>(ze, zsq, B_);
    rowsumsq_kernel<<<(KC * 32) / 256, 256>>>(embed, esq, KC);

    // distance + argmin
    {
        int smem = 2 * 256 * 64 * (int)sizeof(float);  // 128 KB
        cudaFuncSetAttribute(dist_argmin_kernel,
                             cudaFuncAttributeMaxDynamicSharedMemorySize, smem);
        dist_argmin_kernel<<<B_ / 64, 256, smem>>>(embed);
    }

    // gather + loss
    gather_loss_kernel<<<(B_ * 32) / 256, 256>>>(embed, out, write_extra);
    loss_final_kernel<<<1, 256>>>(out, write_extra);

    // decoder (straight-through forward value is z_q)
    {
        dim3 g(HID / 128, B_ / 128);
        sgemm_bias_act<true><<<g, 256>>>(zq, D1, d1, h1, B_, HID, LAT);
    }
    {
        dim3 g(HID / 128, B_ / 128);
        sgemm_bias_act<true><<<g, 256>>>(h1, D2, d2, h2, B_, HID, HID);
    }
    {
        dim3 g(DIN / 128, B_ / 128);
        sgemm_bias_act<false><<<g, 256>>>(h2, D3, d3, out, B_, DIN, HID);
    }
}

// round 2
// speedup vs baseline: 1.1119x; 1.1119x over previous
#include <cuda_runtime.h>
#include <math.h>

#define B_   8192
#define DIN  1024
#define HID  2048
#define LAT  256
#define KC   4096

typedef unsigned long long ull;

// ---------------- scratch (device globals; no allocation allowed) ----------
__device__ float g_h1[(size_t)B_ * HID];   // 64 MB
__device__ float g_h2[(size_t)B_ * HID];   // 64 MB
__device__ float g_ze[(size_t)B_ * LAT];   // 8 MB
__device__ float g_zq[(size_t)B_ * LAT];   // 8 MB
__device__ float g_zsq[B_];
__device__ float g_esq[KC];
__device__ float g_rowloss[B_];
__device__ int   g_idx[B_];

__device__ __forceinline__ float gelu_exact(float x) {
    return 0.5f * x * (1.0f + erff(x * 0.7071067811865476f));
}

// packed fp32x2 FMA: two independent rn-rounded fp32 FMAs (FFMA2)
__device__ __forceinline__ void fma2(ull& d, ull a, ull b, ull c) {
    asm("fma.rn.f32x2 %0, %1, %2, %3;" : "=l"(d) : "l"(a), "l"(b), "l"(c));
}
__device__ __forceinline__ ull pack2(float lo, float hi) {
    ull r;
    asm("mov.b64 %0, {%1, %2};" : "=l"(r) : "f"(lo), "f"(hi));
    return r;
}
__device__ __forceinline__ void unpack2(ull v, float& lo, float& hi) {
    asm("mov.b64 {%0, %1}, %2;" : "=f"(lo), "=f"(hi) : "l"(v));
}

// ---------------- SGEMM: C = act(A[M,K] @ B[K,N] + bias) --------------------
// 128x128 tile, BK=8, 256 threads, 8x8 per thread via FFMA2 (pairs along j).
// Bitwise identical to scalar FFMA version (same per-accumulator k-order).
template<bool GELU>
__global__ void __launch_bounds__(256, 2) sgemm_bias_act(
    const float* __restrict__ A, const float* __restrict__ Bm,
    const float* __restrict__ bias, float* __restrict__ C,
    int M, int N, int K)
{
    __shared__ float As[8][128];
    __shared__ float Bs[8][128];

    const int tid = threadIdx.x;
    const int bm = blockIdx.y * 128;
    const int bn = blockIdx.x * 128;

    const int arow = tid >> 1;            // 0..127
    const int acol = (tid & 1) * 4;       // 0 or 4
    const int brow = tid >> 5;            // 0..7
    const int bcol = (tid & 31) * 4;      // 0..124

    const int ty = tid >> 4;              // 0..15
    const int tx = tid & 15;              // 0..15

    ull acc2[8][4];
#pragma unroll
    for (int i = 0; i < 8; i++)
#pragma unroll
        for (int j = 0; j < 4; j++) acc2[i][j] = 0ull;

    const float* Aptr = A + (size_t)(bm + arow) * K + acol;
    const float* Bptr = Bm + (size_t)brow * N + bn + bcol;

    for (int k0 = 0; k0 < K; k0 += 8) {
        float4 a4 = *(const float4*)(Aptr + k0);
        As[acol + 0][arow] = a4.x;
        As[acol + 1][arow] = a4.y;
        As[acol + 2][arow] = a4.z;
        As[acol + 3][arow] = a4.w;
        float4 b4 = *(const float4*)(Bptr + (size_t)k0 * N);
        *(float4*)&Bs[brow][bcol] = b4;
        __syncthreads();

#pragma unroll
        for (int kk = 0; kk < 8; kk++) {
            float ra[8];
            *(float4*)(ra)     = *(const float4*)&As[kk][ty * 8];
            *(float4*)(ra + 4) = *(const float4*)&As[kk][ty * 8 + 4];
            ull rb2[4];
            *(uint4*)&rb2[0] = *(const uint4*)&Bs[kk][tx * 8];
            *(uint4*)&rb2[2] = *(const uint4*)&Bs[kk][tx * 8 + 4];
#pragma unroll
            for (int i = 0; i < 8; i++) {
                ull a2 = pack2(ra[i], ra[i]);
#pragma unroll
                for (int j = 0; j < 4; j++)
                    fma2(acc2[i][j], a2, rb2[j], acc2[i][j]);
            }
        }
        __syncthreads();
    }

#pragma unroll
    for (int i = 0; i < 8; i++) {
        int row = bm + ty * 8 + i;
#pragma unroll
        for (int j = 0; j < 4; j += 2) {
            int col = bn + tx * 8 + j * 2;
            float4 v;
            unpack2(acc2[i][j],     v.x, v.y);
            unpack2(acc2[i][j + 1], v.z, v.w);
            v.x += bias[col + 0];
            v.y += bias[col + 1];
            v.z += bias[col + 2];
            v.w += bias[col + 3];
            if (GELU) {
                v.x = gelu_exact(v.x); v.y = gelu_exact(v.y);
                v.z = gelu_exact(v.z); v.w = gelu_exact(v.w);
            }
            *(float4*)(C + (size_t)row * N + col) = v;
        }
    }
}

// ---------------- per-row sum of squares (one warp per row) ----------------
__global__ void rowsumsq_kernel(const float* __restrict__ src,
                                float* __restrict__ out, int rows)
{
    int warp = (blockIdx.x * blockDim.x + threadIdx.x) >> 5;
    int lane = threadIdx.x & 31;
    if (warp >= rows) return;
    const float* p = src + (size_t)warp * LAT;
    float s = 0.0f;
#pragma unroll
    for (int i = 0; i < LAT; i += 32) {
        float v = p[i + lane];
        s = fmaf(v, v, s);
    }
#pragma unroll
    for (int o = 16; o; o >>= 1) s += __shfl_down_sync(0xffffffffu, s, o);
    if (lane == 0) out[warp] = s;
}

// ---------------- distance + argmin: 64 rows x 4096 codes per block --------
// dist = (zsq + esq) - 2*dot, rounded exactly like the reference's
// elementwise expression. First-index tie-break. FFMA2 inner product
// (pairs along code dim; bitwise identical accumulation per (row,code)).
__global__ void __launch_bounds__(256) dist_argmin_kernel(
    const float* __restrict__ embed)
{
    extern __shared__ float sm[];
    float* Zs = sm;                 // [256][64] k-major
    float* Es = sm + 256 * 64;      // [256][64] k-major

    const int tid = threadIdx.x;
    const int row0 = blockIdx.x * 64;

    for (int t = tid; t < 64 * 64; t += 256) {
        int r  = t & 63;
        int kq = t >> 6;
        float4 v = *(const float4*)(&g_ze[(size_t)(row0 + r) * LAT + kq * 4]);
        Zs[(kq * 4 + 0) * 64 + r] = v.x;
        Zs[(kq * 4 + 1) * 64 + r] = v.y;
        Zs[(kq * 4 + 2) * 64 + r] = v.z;
        Zs[(kq * 4 + 3) * 64 + r] = v.w;
    }

    const int ty = tid >> 4, tx = tid & 15;
    float bestv[4];
    int   besti[4];
#pragma unroll
    for (int i = 0; i < 4; i++) { bestv[i] = INFINITY; besti[i] = 0; }

    float zs[4];
#pragma unroll
    for (int i = 0; i < 4; i++) zs[i] = g_zsq[row0 + ty * 4 + i];

    for (int c0 = 0; c0 < KC; c0 += 64) {
        __syncthreads();
        for (int t = tid; t < 64 * 64; t += 256) {
            int r  = t & 63;
            int kq = t >> 6;
            float4 v = *(const float4*)(&embed[(size_t)(c0 + r) * LAT + kq * 4]);
            Es[(kq * 4 + 0) * 64 + r] = v.x;
            Es[(kq * 4 + 1) * 64 + r] = v.y;
            Es[(kq * 4 + 2) * 64 + r] = v.z;
            Es[(kq * 4 + 3) * 64 + r] = v.w;
        }
        __syncthreads();

        ull acc2[4][2];
#pragma unroll
        for (int i = 0; i < 4; i++)
#pragma unroll
            for (int j = 0; j < 2; j++) acc2[i][j] = 0ull;

        for (int k = 0; k < 256; k++) {
            float rz[4];
            *(float4*)rz = *(const float4*)&Zs[k * 64 + ty * 4];
            ull re2[2];
            *(uint4*)&re2[0] = *(const uint4*)&Es[k * 64 + tx * 4];
#pragma unroll
            for (int i = 0; i < 4; i++) {
                ull z2 = pack2(rz[i], rz[i]);
#pragma unroll
                for (int j = 0; j < 2; j++)
                    fma2(acc2[i][j], z2, re2[j], acc2[i][j]);
            }
        }

#pragma unroll
        for (int i = 0; i < 4; i++) {
            float dot[4];
            unpack2(acc2[i][0], dot[0], dot[1]);
            unpack2(acc2[i][1], dot[2], dot[3]);
#pragma unroll
            for (int j = 0; j < 4; j++) {
                int c = c0 + tx * 4 + j;
                float t1 = zs[i] + g_esq[c];           // fl(z_sq + e_sq)
                float v  = fmaf(-2.0f, dot[j], t1);    // fl(t1 - 2*dot)
                if (v < bestv[i] || (v == bestv[i] && c < besti[i])) {
                    bestv[i] = v; besti[i] = c;
                }
            }
        }
    }

    __syncthreads();
    float* sval = Es;
    int*   sidx = (int*)(Es + 64 * 16);
#pragma unroll
    for (int i = 0; i < 4; i++) {
        sval[(ty * 4 + i) * 16 + tx] = bestv[i];
        sidx[(ty * 4 + i) * 16 + tx] = besti[i];
    }
    __syncthreads();
    if (tid < 64) {
        float bv = INFINITY; int bi = 0x7fffffff;
        for (int t = 0; t < 16; t++) {
            float v = sval[tid * 16 + t];
            int   c = sidx[tid * 16 + t];
            if (v < bv || (v == bv && c < bi)) { bv = v; bi = c; }
        }
        g_idx[row0 + tid] = bi;
    }
}

// ---------------- gather z_q, per-row loss, indices out --------------------
__global__ void gather_loss_kernel(const float* __restrict__ embed,
                                   float* __restrict__ out_f, int write_extra)
{
    int warp = (blockIdx.x * blockDim.x + threadIdx.x) >> 5;
    int lane = threadIdx.x & 31;
    if (warp >= B_) return;
    int idx = g_idx[warp];
    const float* ze = g_ze + (size_t)warp * LAT;
    const float* eq = embed + (size_t)idx * LAT;
    float s = 0.0f;
#pragma unroll
    for (int i = 0; i < LAT; i += 32) {
        float q = eq[i + lane];
        float z = ze[i + lane];
        g_zq[(size_t)warp * LAT + i + lane] = q;
        float d = z - q;
        s = fmaf(d, d, s);
    }
#pragma unroll
    for (int o = 16; o; o >>= 1) s += __shfl_down_sync(0xffffffffu, s, o);
    if (lane == 0) {
        g_rowloss[warp] = s;
        if (write_extra)
            out_f[(size_t)B_ * DIN + 1 + warp] = (float)idx;
    }
}

// ---------------- final loss reduction (single block, fixed order) ---------
__global__ void loss_final_kernel(float* __restrict__ out_f, int write_extra)
{
    __shared__ float sh[256];
    float s = 0.0f;
    for (int i = threadIdx.x; i < B_; i += 256) s += g_rowloss[i];
    sh[threadIdx.x] = s;
    __syncthreads();
    for (int o = 128; o; o >>= 1) {
        if (threadIdx.x < o) sh[threadIdx.x] += sh[threadIdx.x + o];
        __syncthreads();
    }
    if (threadIdx.x == 0 && write_extra) {
        out_f[(size_t)B_ * DIN] = 1.25f * sh[0] / (float)((size_t)B_ * LAT);
    }
}

// ---------------- launch ----------------------------------------------------
extern "C" void kernel_launch(void* const* d_in, const int* in_sizes, int n_in,
                              void* d_out, int out_size)
{
    const float* x     = (const float*)d_in[0];
    const float* W1    = (const float*)d_in[1];
    const float* b1    = (const float*)d_in[2];
    const float* W2    = (const float*)d_in[3];
    const float* b2    = (const float*)d_in[4];
    const float* W3    = (const float*)d_in[5];
    const float* b3    = (const float*)d_in[6];
    const float* embed = (const float*)d_in[7];
    const float* D1    = (const float*)d_in[8];
    const float* d1    = (const float*)d_in[9];
    const float* D2    = (const float*)d_in[10];
    const float* d2    = (const float*)d_in[11];
    const float* D3    = (const float*)d_in[12];
    const float* d3    = (const float*)d_in[13];
    float* out = (float*)d_out;

    float *h1, *h2, *ze, *zq, *zsq, *esq;
    cudaGetSymbolAddress((void**)&h1,  g_h1);
    cudaGetSymbolAddress((void**)&h2,  g_h2);
    cudaGetSymbolAddress((void**)&ze,  g_ze);
    cudaGetSymbolAddress((void**)&zq,  g_zq);
    cudaGetSymbolAddress((void**)&zsq, g_zsq);
    cudaGetSymbolAddress((void**)&esq, g_esq);

    const int write_extra =
        ((size_t)out_size >= (size_t)B_ * DIN + 1 + B_) ? 1 : 0;

    // encoder
    {
        dim3 g(HID / 128, B_ / 128);
        sgemm_bias_act<true><<<g, 256>>>(x, W1, b1, h1, B_, HID, DIN);
    }
    {
        dim3 g(HID / 128, B_ / 128);
        sgemm_bias_act<true><<<g, 256>>>(h1, W2, b2, h2, B_, HID, HID);
    }
    {
        dim3 g(LAT / 128, B_ / 128);
        sgemm_bias_act<false><<<g, 256>>>(h2, W3, b3, ze, B_, LAT, HID);
    }

    // norms
    rowsumsq_kernel<<<(B_ * 32) / 256, 256>>>(ze, zsq, B_);
    rowsumsq_kernel<<<(KC * 32) / 256, 256>>>(embed, esq, KC);

    // distance + argmin
    {
        int smem = 2 * 256 * 64 * (int)sizeof(float);  // 128 KB
        cudaFuncSetAttribute(dist_argmin_kernel,
                             cudaFuncAttributeMaxDynamicSharedMemorySize, smem);
        dist_argmin_kernel<<<B_ / 64, 256, smem>>>(embed);
    }

    // gather + loss
    gather_loss_kernel<<<(B_ * 32) / 256, 256>>>(embed, out, write_extra);
    loss_final_kernel<<<1, 256>>>(out, write_extra);

    // decoder (straight-through forward value is z_q)
    {
        dim3 g(HID / 128, B_ / 128);
        sgemm_bias_act<true><<<g, 256>>>(zq, D1, d1, h1, B_, HID, LAT);
    }
    {
        dim3 g(HID / 128, B_ / 128);
        sgemm_bias_act<true><<<g, 256>>>(h1, D2, d2, h2, B_, HID, HID);
    }
    {
        dim3 g(DIN / 128, B_ / 128);
        sgemm_bias_act<false><<<g, 256>>>(h2, D3, d3, out, B_, DIN, HID);
    }
}

// round 4
// speedup vs baseline: 1.2486x; 1.1229x over previous
#include <cuda_runtime.h>
#include <math.h>
#include <stdint.h>

#define B_   8192
#define DIN  1024
#define HID  2048
#define LAT  256
#define KC   4096

typedef unsigned long long ull;

// ---------------- scratch (device globals; no allocation allowed) ----------
__device__ float g_h1[(size_t)B_ * HID];   // 64 MB
__device__ float g_h2[(size_t)B_ * HID];   // 64 MB
__device__ float g_ze[(size_t)B_ * LAT];   // 8 MB
__device__ float g_zq[(size_t)B_ * LAT];   // 8 MB
__device__ float g_zsq[B_];
__device__ float g_esq[KC];
__device__ float g_rowloss[B_];
__device__ int   g_idx[B_];

__device__ __forceinline__ float gelu_exact(float x) {
    return 0.5f * x * (1.0f + erff(x * 0.7071067811865476f));
}

// packed fp32x2 FMA: two independent rn-rounded fp32 FMAs (FFMA2)
__device__ __forceinline__ void fma2(ull& d, ull a, ull b, ull c) {
    asm("fma.rn.f32x2 %0, %1, %2, %3;" : "=l"(d) : "l"(a), "l"(b), "l"(c));
}
__device__ __forceinline__ ull pack2(float lo, float hi) {
    ull r;
    asm("mov.b64 %0, {%1, %2};" : "=l"(r) : "f"(lo), "f"(hi));
    return r;
}
__device__ __forceinline__ void unpack2(ull v, float& lo, float& hi) {
    asm("mov.b64 {%0, %1}, %2;" : "=f"(lo), "=f"(hi) : "l"(v));
}

// ================= EXACT encoder GEMM (FFMA2; bit-identical to Round 2) ====
template<bool GELU>
__global__ void __launch_bounds__(256, 2) sgemm_bias_act(
    const float* __restrict__ A, const float* __restrict__ Bm,
    const float* __restrict__ bias, float* __restrict__ C,
    int M, int N, int K)
{
    __shared__ float As[8][128];
    __shared__ float Bs[8][128];

    const int tid = threadIdx.x;
    const int bm = blockIdx.y * 128;
    const int bn = blockIdx.x * 128;

    const int arow = tid >> 1;
    const int acol = (tid & 1) * 4;
    const int brow = tid >> 5;
    const int bcol = (tid & 31) * 4;

    const int ty = tid >> 4;
    const int tx = tid & 15;

    ull acc2[8][4];
#pragma unroll
    for (int i = 0; i < 8; i++)
#pragma unroll
        for (int j = 0; j < 4; j++) acc2[i][j] = 0ull;

    const float* Aptr = A + (size_t)(bm + arow) * K + acol;
    const float* Bptr = Bm + (size_t)brow * N + bn + bcol;

    for (int k0 = 0; k0 < K; k0 += 8) {
        float4 a4 = *(const float4*)(Aptr + k0);
        As[acol + 0][arow] = a4.x;
        As[acol + 1][arow] = a4.y;
        As[acol + 2][arow] = a4.z;
        As[acol + 3][arow] = a4.w;
        float4 b4 = *(const float4*)(Bptr + (size_t)k0 * N);
        *(float4*)&Bs[brow][bcol] = b4;
        __syncthreads();

#pragma unroll
        for (int kk = 0; kk < 8; kk++) {
            float ra[8];
            *(float4*)(ra)     = *(const float4*)&As[kk][ty * 8];
            *(float4*)(ra + 4) = *(const float4*)&As[kk][ty * 8 + 4];
            ull rb2[4];
            *(uint4*)&rb2[0] = *(const uint4*)&Bs[kk][tx * 8];
            *(uint4*)&rb2[2] = *(const uint4*)&Bs[kk][tx * 8 + 4];
#pragma unroll
            for (int i = 0; i < 8; i++) {
                ull a2 = pack2(ra[i], ra[i]);
#pragma unroll
                for (int j = 0; j < 4; j++)
                    fma2(acc2[i][j], a2, rb2[j], acc2[i][j]);
            }
        }
        __syncthreads();
    }

#pragma unroll
    for (int i = 0; i < 8; i++) {
        int row = bm + ty * 8 + i;
#pragma unroll
        for (int j = 0; j < 4; j += 2) {
            int col = bn + tx * 8 + j * 2;
            float4 v;
            unpack2(acc2[i][j],     v.x, v.y);
            unpack2(acc2[i][j + 1], v.z, v.w);
            v.x += bias[col + 0];
            v.y += bias[col + 1];
            v.z += bias[col + 2];
            v.w += bias[col + 3];
            if (GELU) {
                v.x = gelu_exact(v.x); v.y = gelu_exact(v.y);
                v.z = gelu_exact(v.z); v.w = gelu_exact(v.w);
            }
            *(float4*)(C + (size_t)row * N + col) = v;
        }
    }
}

// ================= 3xTF32 tensor-core GEMM (decoder only) ==================
__device__ __forceinline__ void split_tf32(float x, uint32_t& hi, uint32_t& lo) {
    asm("cvt.rna.tf32.f32 %0, %1;" : "=r"(hi) : "f"(x));
    float r = x - __uint_as_float(hi);
    asm("cvt.rna.tf32.f32 %0, %1;" : "=r"(lo) : "f"(r));
}

__device__ __forceinline__ void mma8(float* d, const uint32_t* a, const uint32_t* b) {
    asm("mma.sync.aligned.m16n8k8.row.col.f32.tf32.tf32.f32 "
        "{%0,%1,%2,%3}, {%4,%5,%6,%7}, {%8,%9}, {%0,%1,%2,%3};"
        : "+f"(d[0]), "+f"(d[1]), "+f"(d[2]), "+f"(d[3])
        : "r"(a[0]), "r"(a[1]), "r"(a[2]), "r"(a[3]), "r"(b[0]), "r"(b[1]));
}

#define SMA_HI 0
#define SMA_LO 4608            // 128*36
#define SMB_HI 9216
#define SMB_LO 13440           // + 32*132
#define SM_U32 17664
#define SM_BYTES (SM_U32 * 4)

template<bool GELU>
__global__ void __launch_bounds__(256) mma_gemm_bias_act(
    const float* __restrict__ A, const float* __restrict__ Bm,
    const float* __restrict__ bias, float* __restrict__ C,
    int M, int N, int K)
{
    extern __shared__ uint32_t smu[];
    uint32_t* As_hi = smu + SMA_HI;   // [128][36]
    uint32_t* As_lo = smu + SMA_LO;
    uint32_t* Bs_hi = smu + SMB_HI;   // [32][132]
    uint32_t* Bs_lo = smu + SMB_LO;

    const int tid  = threadIdx.x;
    const int wid  = tid >> 5;
    const int lane = tid & 31;
    const int g = lane >> 2;
    const int t = lane & 3;
    const int warp_m = wid & 1;
    const int warp_n = wid >> 1;
    const int bm = blockIdx.y * 128;
    const int bn = blockIdx.x * 128;

    float acc[4][4][4];
#pragma unroll
    for (int i = 0; i < 4; i++)
#pragma unroll
        for (int j = 0; j < 4; j++)
#pragma unroll
            for (int r = 0; r < 4; r++) acc[i][j][r] = 0.0f;

    const int ar  = tid >> 3;
    const int ac4 = (tid & 7) * 4;
    const int bk  = tid >> 5;
    const int bc4 = lane * 4;

    float4 pa[4], pb[4];
#pragma unroll
    for (int i = 0; i < 4; i++)
        pa[i] = *(const float4*)&A[(size_t)(bm + ar + i * 32) * K + ac4];
#pragma unroll
    for (int i = 0; i < 4; i++)
        pb[i] = *(const float4*)&Bm[(size_t)(bk + i * 8) * N + bn + bc4];

    for (int k0 = 0; k0 < K; k0 += 32) {
#pragma unroll
        for (int i = 0; i < 4; i++) {
            int row = ar + i * 32;
            float v[4] = { pa[i].x, pa[i].y, pa[i].z, pa[i].w };
#pragma unroll
            for (int j = 0; j < 4; j++) {
                uint32_t hi, lo;
                split_tf32(v[j], hi, lo);
                As_hi[row * 36 + ac4 + j] = hi;
                As_lo[row * 36 + ac4 + j] = lo;
            }
        }
#pragma unroll
        for (int i = 0; i < 4; i++) {
            int k = bk + i * 8;
            float v[4] = { pb[i].x, pb[i].y, pb[i].z, pb[i].w };
#pragma unroll
            for (int j = 0; j < 4; j++) {
                uint32_t hi, lo;
                split_tf32(v[j], hi, lo);
                Bs_hi[k * 132 + bc4 + j] = hi;
                Bs_lo[k * 132 + bc4 + j] = lo;
            }
        }
        __syncthreads();

        if (k0 + 32 < K) {
#pragma unroll
            for (int i = 0; i < 4; i++)
                pa[i] = *(const float4*)&A[(size_t)(bm + ar + i * 32) * K + k0 + 32 + ac4];
#pragma unroll
            for (int i = 0; i < 4; i++)
                pb[i] = *(const float4*)&Bm[(size_t)(k0 + 32 + bk + i * 8) * N + bn + bc4];
        }

#pragma unroll
        for (int k8 = 0; k8 < 4; k8++) {
            const int kk = k8 * 8;
            uint32_t ah[4][4], al[4][4], bh[4][2], bl[4][2];
#pragma unroll
            for (int im = 0; im < 4; im++) {
                int row = warp_m * 64 + im * 16 + g;
                ah[im][0] = As_hi[row * 36 + kk + t];
                ah[im][1] = As_hi[(row + 8) * 36 + kk + t];
                ah[im][2] = As_hi[row * 36 + kk + t + 4];
                ah[im][3] = As_hi[(row + 8) * 36 + kk + t + 4];
                al[im][0] = As_lo[row * 36 + kk + t];
                al[im][1] = As_lo[(row + 8) * 36 + kk + t];
                al[im][2] = As_lo[row * 36 + kk + t + 4];
                al[im][3] = As_lo[(row + 8) * 36 + kk + t + 4];
            }
#pragma unroll
            for (int jn = 0; jn < 4; jn++) {
                int col = warp_n * 32 + jn * 8 + g;
                bh[jn][0] = Bs_hi[(kk + t) * 132 + col];
                bh[jn][1] = Bs_hi[(kk + t + 4) * 132 + col];
                bl[jn][0] = Bs_lo[(kk + t) * 132 + col];
                bl[jn][1] = Bs_lo[(kk + t + 4) * 132 + col];
            }
#pragma unroll
            for (int im = 0; im < 4; im++)
#pragma unroll
                for (int jn = 0; jn < 4; jn++) {
                    mma8(acc[im][jn], al[im], bh[jn]);
                    mma8(acc[im][jn], ah[im], bl[jn]);
                    mma8(acc[im][jn], ah[im], bh[jn]);
                }
        }
        __syncthreads();
    }

#pragma unroll
    for (int im = 0; im < 4; im++) {
#pragma unroll
        for (int jn = 0; jn < 4; jn++) {
            int row = bm + warp_m * 64 + im * 16 + g;
            int col = bn + warp_n * 32 + jn * 8 + 2 * t;
            float bx = bias[col], by = bias[col + 1];
            float2 v0, v1;
            v0.x = acc[im][jn][0] + bx;
            v0.y = acc[im][jn][1] + by;
            v1.x = acc[im][jn][2] + bx;
            v1.y = acc[im][jn][3] + by;
            if (GELU) {
                v0.x = gelu_exact(v0.x); v0.y = gelu_exact(v0.y);
                v1.x = gelu_exact(v1.x); v1.y = gelu_exact(v1.y);
            }
            *(float2*)&C[(size_t)row * N + col] = v0;
            *(float2*)&C[(size_t)(row + 8) * N + col] = v1;
        }
    }
}

// ---------------- per-row sum of squares (one warp per row) ----------------
__global__ void rowsumsq_kernel(const float* __restrict__ src,
                                float* __restrict__ out, int rows)
{
    int warp = (blockIdx.x * blockDim.x + threadIdx.x) >> 5;
    int lane = threadIdx.x & 31;
    if (warp >= rows) return;
    const float* p = src + (size_t)warp * LAT;
    float s = 0.0f;
#pragma unroll
    for (int i = 0; i < LAT; i += 32) {
        float v = p[i + lane];
        s = fmaf(v, v, s);
    }
#pragma unroll
    for (int o = 16; o; o >>= 1) s += __shfl_down_sync(0xffffffffu, s, o);
    if (lane == 0) out[warp] = s;
}

// ---------------- distance + argmin: 64 rows x 4096 codes per block --------
__global__ void __launch_bounds__(256) dist_argmin_kernel(
    const float* __restrict__ embed)
{
    extern __shared__ float sm[];
    float* Zs = sm;
    float* Es = sm + 256 * 64;

    const int tid = threadIdx.x;
    const int row0 = blockIdx.x * 64;

    for (int tt = tid; tt < 64 * 64; tt += 256) {
        int r  = tt & 63;
        int kq = tt >> 6;
        float4 v = *(const float4*)(&g_ze[(size_t)(row0 + r) * LAT + kq * 4]);
        Zs[(kq * 4 + 0) * 64 + r] = v.x;
        Zs[(kq * 4 + 1) * 64 + r] = v.y;
        Zs[(kq * 4 + 2) * 64 + r] = v.z;
        Zs[(kq * 4 + 3) * 64 + r] = v.w;
    }

    const int ty = tid >> 4, tx = tid & 15;
    float bestv[4];
    int   besti[4];
#pragma unroll
    for (int i = 0; i < 4; i++) { bestv[i] = INFINITY; besti[i] = 0; }

    float zs[4];
#pragma unroll
    for (int i = 0; i < 4; i++) zs[i] = g_zsq[row0 + ty * 4 + i];

    for (int c0 = 0; c0 < KC; c0 += 64) {
        __syncthreads();
        for (int tt = tid; tt < 64 * 64; tt += 256) {
            int r  = tt & 63;
            int kq = tt >> 6;
            float4 v = *(const float4*)(&embed[(size_t)(c0 + r) * LAT + kq * 4]);
            Es[(kq * 4 + 0) * 64 + r] = v.x;
            Es[(kq * 4 + 1) * 64 + r] = v.y;
            Es[(kq * 4 + 2) * 64 + r] = v.z;
            Es[(kq * 4 + 3) * 64 + r] = v.w;
        }
        __syncthreads();

        ull acc2[4][2];
#pragma unroll
        for (int i = 0; i < 4; i++)
#pragma unroll
            for (int j = 0; j < 2; j++) acc2[i][j] = 0ull;

        for (int k = 0; k < 256; k++) {
            float rz[4];
            *(float4*)rz = *(const float4*)&Zs[k * 64 + ty * 4];
            ull re2[2];
            *(uint4*)&re2[0] = *(const uint4*)&Es[k * 64 + tx * 4];
#pragma unroll
            for (int i = 0; i < 4; i++) {
                ull z2 = pack2(rz[i], rz[i]);
#pragma unroll
                for (int j = 0; j < 2; j++)
                    fma2(acc2[i][j], z2, re2[j], acc2[i][j]);
            }
        }

#pragma unroll
        for (int i = 0; i < 4; i++) {
            float dot[4];
            unpack2(acc2[i][0], dot[0], dot[1]);
            unpack2(acc2[i][1], dot[2], dot[3]);
#pragma unroll
            for (int j = 0; j < 4; j++) {
                int c = c0 + tx * 4 + j;
                float t1 = zs[i] + g_esq[c];
                float v  = fmaf(-2.0f, dot[j], t1);
                if (v < bestv[i] || (v == bestv[i] && c < besti[i])) {
                    bestv[i] = v; besti[i] = c;
                }
            }
        }
    }

    __syncthreads();
    float* sval = Es;
    int*   sidx = (int*)(Es + 64 * 16);
#pragma unroll
    for (int i = 0; i < 4; i++) {
        sval[(ty * 4 + i) * 16 + tx] = bestv[i];
        sidx[(ty * 4 + i) * 16 + tx] = besti[i];
    }
    __syncthreads();
    if (tid < 64) {
        float bv = INFINITY; int bi = 0x7fffffff;
        for (int tt = 0; tt < 16; tt++) {
            float v = sval[tid * 16 + tt];
            int   c = sidx[tid * 16 + tt];
            if (v < bv || (v == bv && c < bi)) { bv = v; bi = c; }
        }
        g_idx[row0 + tid] = bi;
    }
}

// ---------------- gather z_q, per-row loss, indices out --------------------
__global__ void gather_loss_kernel(const float* __restrict__ embed,
                                   float* __restrict__ out_f, int write_extra)
{
    int warp = (blockIdx.x * blockDim.x + threadIdx.x) >> 5;
    int lane = threadIdx.x & 31;
    if (warp >= B_) return;
    int idx = g_idx[warp];
    const float* ze = g_ze + (size_t)warp * LAT;
    const float* eq = embed + (size_t)idx * LAT;
    float s = 0.0f;
#pragma unroll
    for (int i = 0; i < LAT; i += 32) {
        float q = eq[i + lane];
        float z = ze[i + lane];
        g_zq[(size_t)warp * LAT + i + lane] = q;
        float d = z - q;
        s = fmaf(d, d, s);
    }
#pragma unroll
    for (int o = 16; o; o >>= 1) s += __shfl_down_sync(0xffffffffu, s, o);
    if (lane == 0) {
        g_rowloss[warp] = s;
        if (write_extra)
            out_f[(size_t)B_ * DIN + 1 + warp] = (float)idx;
    }
}

// ---------------- final loss reduction (single block, fixed order) ---------
__global__ void loss_final_kernel(float* __restrict__ out_f, int write_extra)
{
    __shared__ float sh[256];
    float s = 0.0f;
    for (int i = threadIdx.x; i < B_; i += 256) s += g_rowloss[i];
    sh[threadIdx.x] = s;
    __syncthreads();
    for (int o = 128; o; o >>= 1) {
        if (threadIdx.x < o) sh[threadIdx.x] += sh[threadIdx.x + o];
        __syncthreads();
    }
    if (threadIdx.x == 0 && write_extra) {
        out_f[(size_t)B_ * DIN] = 1.25f * sh[0] / (float)((size_t)B_ * LAT);
    }
}

// ---------------- launch ----------------------------------------------------
extern "C" void kernel_launch(void* const* d_in, const int* in_sizes, int n_in,
                              void* d_out, int out_size)
{
    const float* x     = (const float*)d_in[0];
    const float* W1    = (const float*)d_in[1];
    const float* b1    = (const float*)d_in[2];
    const float* W2    = (const float*)d_in[3];
    const float* b2    = (const float*)d_in[4];
    const float* W3    = (const float*)d_in[5];
    const float* b3    = (const float*)d_in[6];
    const float* embed = (const float*)d_in[7];
    const float* D1    = (const float*)d_in[8];
    const float* d1    = (const float*)d_in[9];
    const float* D2    = (const float*)d_in[10];
    const float* d2    = (const float*)d_in[11];
    const float* D3    = (const float*)d_in[12];
    const float* d3    = (const float*)d_in[13];
    float* out = (float*)d_out;

    float *h1, *h2, *ze, *zq, *zsq, *esq;
    cudaGetSymbolAddress((void**)&h1,  g_h1);
    cudaGetSymbolAddress((void**)&h2,  g_h2);
    cudaGetSymbolAddress((void**)&ze,  g_ze);
    cudaGetSymbolAddress((void**)&zq,  g_zq);
    cudaGetSymbolAddress((void**)&zsq, g_zsq);
    cudaGetSymbolAddress((void**)&esq, g_esq);

    const int write_extra =
        ((size_t)out_size >= (size_t)B_ * DIN + 1 + B_) ? 1 : 0;

    cudaFuncSetAttribute(mma_gemm_bias_act<true>,
                         cudaFuncAttributeMaxDynamicSharedMemorySize, SM_BYTES);
    cudaFuncSetAttribute(mma_gemm_bias_act<false>,
                         cudaFuncAttributeMaxDynamicSharedMemorySize, SM_BYTES);

    // encoder — EXACT fp32 (FFMA2): indices bit-identical to Round 2
    {
        dim3 g(HID / 128, B_ / 128);
        sgemm_bias_act<true><<<g, 256>>>(x, W1, b1, h1, B_, HID, DIN);
    }
    {
        dim3 g(HID / 128, B_ / 128);
        sgemm_bias_act<true><<<g, 256>>>(h1, W2, b2, h2, B_, HID, HID);
    }
    {
        dim3 g(LAT / 128, B_ / 128);
        sgemm_bias_act<false><<<g, 256>>>(h2, W3, b3, ze, B_, LAT, HID);
    }

    // norms
    rowsumsq_kernel<<<(B_ * 32) / 256, 256>>>(ze, zsq, B_);
    rowsumsq_kernel<<<(KC * 32) / 256, 256>>>(embed, esq, KC);

    // distance + argmin (exact)
    {
        int smem = 2 * 256 * 64 * (int)sizeof(float);  // 128 KB
        cudaFuncSetAttribute(dist_argmin_kernel,
                             cudaFuncAttributeMaxDynamicSharedMemorySize, smem);
        dist_argmin_kernel<<<B_ / 64, 256, smem>>>(embed);
    }

    // gather + loss
    gather_loss_kernel<<<(B_ * 32) / 256, 256>>>(embed, out, write_extra);
    loss_final_kernel<<<1, 256>>>(out, write_extra);

    // decoder — 3xTF32 tensor cores (no index dependence; ~1e-5 rel error)
    {
        dim3 g(HID / 128, B_ / 128);
        mma_gemm_bias_act<true><<<g, 256, SM_BYTES>>>(zq, D1, d1, h1, B_, HID, LAT);
    }
    {
        dim3 g(HID / 128, B_ / 128);
        mma_gemm_bias_act<true><<<g, 256, SM_BYTES>>>(h1, D2, d2, h2, B_, HID, HID);
    }
    {
        dim3 g(DIN / 128, B_ / 128);
        mma_gemm_bias_act<false><<<g, 256, SM_BYTES>>>(h2, D3, d3, out, B_, DIN, HID);
    }
}